// round 1
// baseline (speedup 1.0000x reference)
#include <cuda_runtime.h>
#include <math.h>

#define NRAYS 2048
#define NS    558
#define RES   160
#define RES2  (160*160)
#define RES3  (160*160*160)
#define STEPW 0.00625f            /* STEPSIZE * VOXEL */
#define NEAR_T 0.05f
#define FAR_T  3.5f
#define ACT_SHIFT_F (-4.595119850134589f)

// scratch (allocation-free: __device__ globals)
__device__ float4 g_samp[NRAYS * NS];     // alpha, r, g, b (pre-sigmoid applied)
__device__ float4 g_rayp[NRAYS];          // tmin, |d|, mask, tmin*|d|
__device__ float  g_embw[NRAYS * 16];     // per-ray emb @ dw1[15:54] + db1

// ---------------------------------------------------------------------------
// Kernel 0: per-ray precompute
// ---------------------------------------------------------------------------
__global__ void ray_pre_kernel(const float* __restrict__ ro,
                               const float* __restrict__ rd,
                               const float* __restrict__ vd,
                               const float* __restrict__ dw1,
                               const float* __restrict__ db1)
{
    int r = blockIdx.x * blockDim.x + threadIdx.x;
    if (r >= NRAYS) return;
    float o[3], d[3], v[3];
#pragma unroll
    for (int c = 0; c < 3; c++) { o[c] = ro[3*r+c]; d[c] = rd[3*r+c]; v[c] = vd[3*r+c]; }

    float tmin = -1e30f, tmax = 1e30f;
#pragma unroll
    for (int c = 0; c < 3; c++) {
        float vec = (d[c] == 0.0f) ? 1e-6f : d[c];
        float ra = ( 1.0f - o[c]) / vec;
        float rb = (-1.0f - o[c]) / vec;
        tmin = fmaxf(tmin, fminf(ra, rb));
        tmax = fminf(tmax, fmaxf(ra, rb));
    }
    tmin = fminf(fmaxf(tmin, NEAR_T), FAR_T);
    tmax = fminf(fmaxf(tmax, NEAR_T), FAR_T);
    float mask = (tmax <= tmin) ? 1.0f : 0.0f;
    float dn = sqrtf(d[0]*d[0] + d[1]*d[1] + d[2]*d[2]);
    g_rayp[r] = make_float4(tmin, dn, mask, tmin * dn);

    // positional encoding of viewdirs: [v, {sin(v*2^l)(3), cos(v*2^l)(3)} for l=0..5]
    float emb[39];
    emb[0] = v[0]; emb[1] = v[1]; emb[2] = v[2];
    int idx = 3;
#pragma unroll
    for (int l = 0; l < 6; l++) {
        float f = (float)(1 << l);
#pragma unroll
        for (int c = 0; c < 3; c++) emb[idx + c]     = sinf(v[c] * f);
#pragma unroll
        for (int c = 0; c < 3; c++) emb[idx + 3 + c] = cosf(v[c] * f);
        idx += 6;
    }
    // per-ray partial of decoder layer 1: rows 15..53 of dw1 (54x16), plus bias
#pragma unroll
    for (int j = 0; j < 16; j++) {
        float acc = db1[j];
#pragma unroll
        for (int e = 0; e < 39; e++) acc += emb[e] * dw1[(15 + e) * 16 + j];
        g_embw[r * 16 + j] = acc;
    }
}

// ---------------------------------------------------------------------------
// Kernel 1: per-sample (block = one ray, 128 threads loop over samples)
// ---------------------------------------------------------------------------
__global__ __launch_bounds__(128) void sample_kernel(
    const float* __restrict__ ro, const float* __restrict__ rd,
    const float* __restrict__ grid,
    const float* __restrict__ aw1, const float* __restrict__ ab1,
    const float* __restrict__ aw2, const float* __restrict__ ab2,
    const float* __restrict__ aw3, const float* __restrict__ ab3,
    const float* __restrict__ pw1, const float* __restrict__ pb1,
    const float* __restrict__ pw2, const float* __restrict__ pb2,
    const float* __restrict__ pw3, const float* __restrict__ pb3,
    const float* __restrict__ dw1, const float* __restrict__ dw2,
    const float* __restrict__ db2, const float* __restrict__ dw3,
    const float* __restrict__ db3, const float* __restrict__ dw4,
    const float* __restrict__ db4)
{
    __shared__ __align__(16) float s_aw1[15*32];
    __shared__ __align__(16) float s_ab1[32];
    __shared__ __align__(16) float s_aw2[32*32];
    __shared__ __align__(16) float s_ab2[32];
    __shared__ __align__(16) float s_aw3[32*4];
    __shared__ __align__(16) float s_ab3[4];
    __shared__ __align__(16) float s_pw1[12*16];
    __shared__ __align__(16) float s_pb1[16];
    __shared__ __align__(16) float s_pw2[16*16];
    __shared__ __align__(16) float s_pb2[16];
    __shared__ __align__(16) float s_pw3[16*16];
    __shared__ __align__(16) float s_pb3[16];
    __shared__ __align__(16) float s_dw1[15*16];   // rows 0..14 of dw1 (contiguous)
    __shared__ __align__(16) float s_dw2[16*16];
    __shared__ __align__(16) float s_db2[16];
    __shared__ __align__(16) float s_dw3[16*16];
    __shared__ __align__(16) float s_db3[16];
    __shared__ __align__(16) float s_dw4[16*3];
    __shared__ __align__(16) float s_db4[4];
    __shared__ __align__(16) float s_embw[16];
    __shared__ __align__(16) float s_rc[12];       // tmin, dn, mask, o(3), d(3)

    const int ray = blockIdx.x;
    const int tid = threadIdx.x;

#define CPW(dst, src, n) for (int i = tid; i < (n); i += 128) (dst)[i] = (src)[i];
    CPW(s_aw1, aw1, 15*32); CPW(s_ab1, ab1, 32);
    CPW(s_aw2, aw2, 32*32); CPW(s_ab2, ab2, 32);
    CPW(s_aw3, aw3, 32*4);  CPW(s_ab3, ab3, 4);
    CPW(s_pw1, pw1, 12*16); CPW(s_pb1, pb1, 16);
    CPW(s_pw2, pw2, 16*16); CPW(s_pb2, pb2, 16);
    CPW(s_pw3, pw3, 16*16); CPW(s_pb3, pb3, 16);
    CPW(s_dw1, dw1, 15*16);
    CPW(s_dw2, dw2, 16*16); CPW(s_db2, db2, 16);
    CPW(s_dw3, dw3, 16*16); CPW(s_db3, db3, 16);
    CPW(s_dw4, dw4, 16*3);  CPW(s_db4, db4, 3);
    CPW(s_embw, g_embw + ray*16, 16);
#undef CPW
    if (tid == 0) {
        float4 rp = g_rayp[ray];
        s_rc[0] = rp.x; s_rc[1] = rp.y; s_rc[2] = rp.z;
        s_rc[3] = ro[3*ray+0]; s_rc[4] = ro[3*ray+1]; s_rc[5] = ro[3*ray+2];
        s_rc[6] = rd[3*ray+0]; s_rc[7] = rd[3*ray+1]; s_rc[8] = rd[3*ray+2];
    }
    __syncthreads();

    const float tmin = s_rc[0], dn = s_rc[1], mask = s_rc[2];
    const float ox = s_rc[3], oy = s_rc[4], oz = s_rc[5];
    const float dx = s_rc[6], dy = s_rc[7], dz = s_rc[8];
    const float inv_dn = 1.0f / dn;

    for (int s = tid; s < NS; s += 128) {
        float4 outv = make_float4(0.0f, 0.0f, 0.0f, 0.0f);
        if (mask == 0.0f) {
            float interpx = tmin + (STEPW * (float)s) * inv_dn;
            float px = fmaf(dx, interpx, ox);
            float py = fmaf(dy, interpx, oy);
            float pz = fmaf(dz, interpx, oz);
            if (fabsf(px) <= 1.0f && fabsf(py) <= 1.0f && fabsf(pz) <= 1.0f) {
                float tx = (px + 1.0f) * 0.5f;
                float ty = (py + 1.0f) * 0.5f;
                float tz = (pz + 1.0f) * 0.5f;
                // trilinear
                float gx = tx * 159.0f, gy = ty * 159.0f, gz = tz * 159.0f;
                float fx0 = floorf(gx), fy0 = floorf(gy), fz0 = floorf(gz);
                float fx = gx - fx0, fy = gy - fy0, fz = gz - fz0;
                int x0 = min(max((int)fx0, 0), RES-1);
                int y0 = min(max((int)fy0, 0), RES-1);
                int z0 = min(max((int)fz0, 0), RES-1);
                int x1 = min(x0 + 1, RES-1);
                int y1 = min(y0 + 1, RES-1);
                int z1 = min(z0 + 1, RES-1);
                int o000 = x0*RES2 + y0*RES + z0;
                int o001 = x0*RES2 + y0*RES + z1;
                int o010 = x0*RES2 + y1*RES + z0;
                int o011 = x0*RES2 + y1*RES + z1;
                int o100 = x1*RES2 + y0*RES + z0;
                int o101 = x1*RES2 + y0*RES + z1;
                int o110 = x1*RES2 + y1*RES + z0;
                int o111 = x1*RES2 + y1*RES + z1;
                float w000 = (1-fx)*(1-fy)*(1-fz);
                float w001 = (1-fx)*(1-fy)*fz;
                float w010 = (1-fx)*fy*(1-fz);
                float w011 = (1-fx)*fy*fz;
                float w100 = fx*(1-fy)*(1-fz);
                float w101 = fx*(1-fy)*fz;
                float w110 = fx*fy*(1-fz);
                float w111 = fx*fy*fz;
                float lat[12];
#pragma unroll
                for (int c = 0; c < 12; c++) {
                    const float* g = grid + c * RES3;
                    lat[c] = g[o000]*w000 + g[o001]*w001 + g[o010]*w010 + g[o011]*w011
                           + g[o100]*w100 + g[o101]*w101 + g[o110]*w110 + g[o111]*w111;
                }

                // ---- attention MLP: in = [flip(t01)*2-1 (3), latent (12)] ----
                float ain[15];
                ain[0] = 2.0f*tz - 1.0f;
                ain[1] = 2.0f*ty - 1.0f;
                ain[2] = 2.0f*tx - 1.0f;
#pragma unroll
                for (int c = 0; c < 12; c++) ain[3+c] = lat[c];

                float h1[32];
#pragma unroll
                for (int j = 0; j < 32; j++) h1[j] = s_ab1[j];
#pragma unroll
                for (int k = 0; k < 15; k++) {
                    float a = ain[k];
#pragma unroll
                    for (int j = 0; j < 32; j++) h1[j] = fmaf(a, s_aw1[k*32+j], h1[j]);
                }
#pragma unroll
                for (int j = 0; j < 32; j++) h1[j] = fmaxf(h1[j], 0.0f);

                float h2[32];
#pragma unroll
                for (int j = 0; j < 32; j++) h2[j] = s_ab2[j];
#pragma unroll
                for (int k = 0; k < 32; k++) {
                    float a = h1[k];
#pragma unroll
                    for (int j = 0; j < 32; j++) h2[j] = fmaf(a, s_aw2[k*32+j], h2[j]);
                }
#pragma unroll
                for (int j = 0; j < 32; j++) h2[j] = fmaxf(h2[j], 0.0f);

                float lg[4];
#pragma unroll
                for (int j = 0; j < 4; j++) lg[j] = s_ab3[j];
#pragma unroll
                for (int k = 0; k < 32; k++) {
                    float a = h2[k];
#pragma unroll
                    for (int j = 0; j < 4; j++) lg[j] = fmaf(a, s_aw3[k*4+j], lg[j]);
                }
                float mx = fmaxf(fmaxf(lg[0], lg[1]), fmaxf(lg[2], lg[3]));
                float e0 = expf(lg[0]-mx), e1 = expf(lg[1]-mx),
                      e2 = expf(lg[2]-mx), e3 = expf(lg[3]-mx);
                float att1 = e1 / (e0 + e1 + e2 + e3);

                // ---- pos MLP (latent -> 16 -> 16 -> 16) ----
                float p1[16];
#pragma unroll
                for (int j = 0; j < 16; j++) p1[j] = s_pb1[j];
#pragma unroll
                for (int k = 0; k < 12; k++) {
                    float a = lat[k];
#pragma unroll
                    for (int j = 0; j < 16; j++) p1[j] = fmaf(a, s_pw1[k*16+j], p1[j]);
                }
#pragma unroll
                for (int j = 0; j < 16; j++) p1[j] = fmaxf(p1[j], 0.0f);

                float p2[16];
#pragma unroll
                for (int j = 0; j < 16; j++) p2[j] = s_pb2[j];
#pragma unroll
                for (int k = 0; k < 16; k++) {
                    float a = p1[k];
#pragma unroll
                    for (int j = 0; j < 16; j++) p2[j] = fmaf(a, s_pw2[k*16+j], p2[j]);
                }
#pragma unroll
                for (int j = 0; j < 16; j++) p2[j] = fmaxf(p2[j], 0.0f);

                float pos[16];
#pragma unroll
                for (int j = 0; j < 16; j++) pos[j] = s_pb3[j];
#pragma unroll
                for (int k = 0; k < 16; k++) {
                    float a = p2[k];
#pragma unroll
                    for (int j = 0; j < 16; j++) pos[j] = fmaf(a, s_pw3[k*16+j], pos[j]);
                }

                // ---- decoder MLP: [pos[1:] (15), emb (39 precomputed)] ----
                float d1[16];
#pragma unroll
                for (int j = 0; j < 16; j++) d1[j] = s_embw[j];
#pragma unroll
                for (int k = 0; k < 15; k++) {
                    float a = pos[k+1];
#pragma unroll
                    for (int j = 0; j < 16; j++) d1[j] = fmaf(a, s_dw1[k*16+j], d1[j]);
                }
#pragma unroll
                for (int j = 0; j < 16; j++) d1[j] = fmaxf(d1[j], 0.0f);

                float d2[16];
#pragma unroll
                for (int j = 0; j < 16; j++) d2[j] = s_db2[j];
#pragma unroll
                for (int k = 0; k < 16; k++) {
                    float a = d1[k];
#pragma unroll
                    for (int j = 0; j < 16; j++) d2[j] = fmaf(a, s_dw2[k*16+j], d2[j]);
                }
#pragma unroll
                for (int j = 0; j < 16; j++) d2[j] = fmaxf(d2[j], 0.0f);

                float d3[16];
#pragma unroll
                for (int j = 0; j < 16; j++) d3[j] = s_db3[j];
#pragma unroll
                for (int k = 0; k < 16; k++) {
                    float a = d2[k];
#pragma unroll
                    for (int j = 0; j < 16; j++) d3[j] = fmaf(a, s_dw3[k*16+j], d3[j]);
                }
#pragma unroll
                for (int j = 0; j < 16; j++) d3[j] = fmaxf(d3[j], 0.0f);

                float rr[3];
#pragma unroll
                for (int j = 0; j < 3; j++) rr[j] = s_db4[j];
#pragma unroll
                for (int k = 0; k < 16; k++) {
                    float a = d3[k];
#pragma unroll
                    for (int j = 0; j < 3; j++) rr[j] = fmaf(a, s_dw4[k*3+j], rr[j]);
                }

                float dens = att1 * pos[0];
                float xs = dens + ACT_SHIFT_F;
                float sp = fmaxf(xs, 0.0f) + log1pf(expf(-fabsf(xs)));
                float alpha = 1.0f - expf(-sp * 0.5f);
                outv.x = alpha;
                outv.y = 1.0f / (1.0f + expf(-att1 * rr[0]));
                outv.z = 1.0f / (1.0f + expf(-att1 * rr[1]));
                outv.w = 1.0f / (1.0f + expf(-att1 * rr[2]));
            }
        }
        g_samp[ray * NS + s] = outv;
    }
}

// ---------------------------------------------------------------------------
// Kernel 2: composite (warp per ray, warp product-scan)
// ---------------------------------------------------------------------------
__global__ void composite_kernel(float* __restrict__ out)
{
    int gwarp = (blockIdx.x * blockDim.x + threadIdx.x) >> 5;
    int lane  = threadIdx.x & 31;
    if (gwarp >= NRAYS) return;
    const int ray = gwarp;
    const float tmindn = g_rayp[ray].w;
    const float4* base = g_samp + ray * NS;

    float T = 1.0f;
    float sr = 0.f, sg = 0.f, sb = 0.f, sd = 0.f, sa = 0.f;

    for (int s0 = 0; s0 < NS; s0 += 32) {
        int s = s0 + lane;
        float4 v = (s < NS) ? base[s] : make_float4(0.f, 0.f, 0.f, 0.f);
        float am = fmaxf(1.0f - v.x, 1e-10f);
        float p = am;
#pragma unroll
        for (int off = 1; off < 32; off <<= 1) {
            float n = __shfl_up_sync(0xffffffffu, p, off);
            if (lane >= off) p *= n;
        }
        float excl = __shfl_up_sync(0xffffffffu, p, 1);
        if (lane == 0) excl = 1.0f;
        float w = v.x * T * excl;
        float depth = tmindn + STEPW * (float)s;
        sr += w * v.y; sg += w * v.z; sb += w * v.w;
        sd += w * depth; sa += w;
        T *= __shfl_sync(0xffffffffu, p, 31);
    }
#pragma unroll
    for (int off = 16; off; off >>= 1) {
        sr += __shfl_xor_sync(0xffffffffu, sr, off);
        sg += __shfl_xor_sync(0xffffffffu, sg, off);
        sb += __shfl_xor_sync(0xffffffffu, sb, off);
        sd += __shfl_xor_sync(0xffffffffu, sd, off);
        sa += __shfl_xor_sync(0xffffffffu, sa, off);
    }
    if (lane == 0) {
        float depthm = sd + T * FAR_T;
        out[ray*6 + 0] = sr + T;   // + T * BG (BG = 1)
        out[ray*6 + 1] = sg + T;
        out[ray*6 + 2] = sb + T;
        out[ray*6 + 3] = depthm;
        out[ray*6 + 4] = 1.0f / depthm;
        out[ray*6 + 5] = sa;
    }
}

// ---------------------------------------------------------------------------
extern "C" void kernel_launch(void* const* d_in, const int* in_sizes, int n_in,
                              void* d_out, int out_size)
{
    const float* ro  = (const float*)d_in[0];
    const float* rd  = (const float*)d_in[1];
    const float* vd  = (const float*)d_in[2];
    const float* grd = (const float*)d_in[3];
    const float* aw1 = (const float*)d_in[4];  const float* ab1 = (const float*)d_in[5];
    const float* aw2 = (const float*)d_in[6];  const float* ab2 = (const float*)d_in[7];
    const float* aw3 = (const float*)d_in[8];  const float* ab3 = (const float*)d_in[9];
    const float* pw1 = (const float*)d_in[10]; const float* pb1 = (const float*)d_in[11];
    const float* pw2 = (const float*)d_in[12]; const float* pb2 = (const float*)d_in[13];
    const float* pw3 = (const float*)d_in[14]; const float* pb3 = (const float*)d_in[15];
    const float* dw1 = (const float*)d_in[16]; const float* db1 = (const float*)d_in[17];
    const float* dw2 = (const float*)d_in[18]; const float* db2 = (const float*)d_in[19];
    const float* dw3 = (const float*)d_in[20]; const float* db3 = (const float*)d_in[21];
    const float* dw4 = (const float*)d_in[22]; const float* db4 = (const float*)d_in[23];
    float* out = (float*)d_out;

    ray_pre_kernel<<<(NRAYS + 255) / 256, 256>>>(ro, rd, vd, dw1, db1);
    sample_kernel<<<NRAYS, 128>>>(ro, rd, grd,
                                  aw1, ab1, aw2, ab2, aw3, ab3,
                                  pw1, pb1, pw2, pb2, pw3, pb3,
                                  dw1, dw2, db2, dw3, db3, dw4, db4);
    composite_kernel<<<(NRAYS * 32) / 256, 256>>>(out);
}

// round 2
// speedup vs baseline: 1.1781x; 1.1781x over previous
#include <cuda_runtime.h>
#include <math.h>

#define NRAYS 2048
#define NS    558
#define RES   160
#define RES2  (160*160)
#define RES3  (160*160*160)
#define STEPW 0.00625f            /* STEPSIZE * VOXEL */
#define FAR_T  3.5f
#define NEAR_T 0.05f
#define ACT_SHIFT_F (-4.595119850134589f)

typedef unsigned long long ull;

__device__ __forceinline__ ull pack2(float lo, float hi) {
    ull r; asm("mov.b64 %0, {%1, %2};" : "=l"(r) : "f"(lo), "f"(hi)); return r;
}
__device__ __forceinline__ void unpack2(ull v, float& lo, float& hi) {
    asm("mov.b64 {%0, %1}, %2;" : "=f"(lo), "=f"(hi) : "l"(v));
}
__device__ __forceinline__ ull fma2(ull a, ull b, ull c) {
    ull r; asm("fma.rn.f32x2 %0, %1, %2, %3;" : "=l"(r) : "l"(a), "l"(b), "l"(c));
    return r;
}

// Packed MLP layer: OUT must be even and multiple of 4 for the quad loads.
template<int IN, int OUT, bool RELU>
__device__ __forceinline__ void mlp_layer(const float* a,
                                          const float* __restrict__ W,
                                          const float* __restrict__ B,
                                          float* out)
{
    constexpr int P = OUT / 2;
    ull h[P];
#pragma unroll
    for (int p = 0; p < P; p++) h[p] = ((const ull*)B)[p];
#pragma unroll
    for (int k = 0; k < IN; k++) {
        ull aa = pack2(a[k], a[k]);
        const ulonglong2* wrow = (const ulonglong2*)(W + k * OUT);
#pragma unroll
        for (int q = 0; q < P / 2; q++) {
            ulonglong2 w = wrow[q];
            h[2*q]     = fma2(aa, w.x, h[2*q]);
            h[2*q + 1] = fma2(aa, w.y, h[2*q + 1]);
        }
    }
#pragma unroll
    for (int p = 0; p < P; p++) {
        float lo, hi; unpack2(h[p], lo, hi);
        out[2*p]     = RELU ? fmaxf(lo, 0.0f) : lo;
        out[2*p + 1] = RELU ? fmaxf(hi, 0.0f) : hi;
    }
}

// ---------------------------------------------------------------------------
// Fused kernel: one block per ray. Per-ray precompute + per-sample MLPs +
// in-block alpha composite.
// ---------------------------------------------------------------------------
__global__ __launch_bounds__(128) void fused_kernel(
    const float* __restrict__ ro, const float* __restrict__ rd,
    const float* __restrict__ vd, const float* __restrict__ grid,
    const float* __restrict__ aw1, const float* __restrict__ ab1,
    const float* __restrict__ aw2, const float* __restrict__ ab2,
    const float* __restrict__ aw3, const float* __restrict__ ab3,
    const float* __restrict__ pw1, const float* __restrict__ pb1,
    const float* __restrict__ pw2, const float* __restrict__ pb2,
    const float* __restrict__ pw3, const float* __restrict__ pb3,
    const float* __restrict__ dw1, const float* __restrict__ db1,
    const float* __restrict__ dw2, const float* __restrict__ db2,
    const float* __restrict__ dw3, const float* __restrict__ db3,
    const float* __restrict__ dw4, const float* __restrict__ db4,
    float* __restrict__ out)
{
    __shared__ __align__(16) float s_aw1[15*32];
    __shared__ __align__(16) float s_ab1[32];
    __shared__ __align__(16) float s_aw2[32*32];
    __shared__ __align__(16) float s_ab2[32];
    __shared__ __align__(16) float s_aw3[32*4];
    __shared__ __align__(16) float s_ab3[4];
    __shared__ __align__(16) float s_pw1[12*16];
    __shared__ __align__(16) float s_pb1[16];
    __shared__ __align__(16) float s_pw2[16*16];
    __shared__ __align__(16) float s_pb2[16];
    __shared__ __align__(16) float s_pw3[16*16];
    __shared__ __align__(16) float s_pb3[16];
    __shared__ __align__(16) float s_dw1[15*16];
    __shared__ __align__(16) float s_dw2[16*16];
    __shared__ __align__(16) float s_db2[16];
    __shared__ __align__(16) float s_dw3[16*16];
    __shared__ __align__(16) float s_db3[16];
    __shared__ __align__(16) float s_dw4[16*3];
    __shared__ __align__(16) float s_db4[4];
    __shared__ __align__(16) float s_embw[16];
    __shared__ __align__(16) float s_rc[12];              // tmin, dn, mask, o(3), d(3)
    __shared__ __align__(16) float4 s_samp[NS];

    const int ray = blockIdx.x;
    const int tid = threadIdx.x;

#define CPW(dst, src, n) for (int i = tid; i < (n); i += 128) (dst)[i] = (src)[i];
    CPW(s_aw1, aw1, 15*32); CPW(s_ab1, ab1, 32);
    CPW(s_aw2, aw2, 32*32); CPW(s_ab2, ab2, 32);
    CPW(s_aw3, aw3, 32*4);  CPW(s_ab3, ab3, 4);
    CPW(s_pw1, pw1, 12*16); CPW(s_pb1, pb1, 16);
    CPW(s_pw2, pw2, 16*16); CPW(s_pb2, pb2, 16);
    CPW(s_pw3, pw3, 16*16); CPW(s_pb3, pb3, 16);
    CPW(s_dw1, dw1, 15*16);
    CPW(s_dw2, dw2, 16*16); CPW(s_db2, db2, 16);
    CPW(s_dw3, dw3, 16*16); CPW(s_db3, db3, 16);
    CPW(s_dw4, dw4, 16*3);  CPW(s_db4, db4, 3);
#undef CPW

    // per-ray viewdir embedding projection: 16 threads, one output each
    if (tid < 16) {
        const int j = tid;
        float v0 = vd[3*ray+0], v1 = vd[3*ray+1], v2 = vd[3*ray+2];
        float acc = db1[j];
        acc += v0 * dw1[(15+0)*16 + j];
        acc += v1 * dw1[(15+1)*16 + j];
        acc += v2 * dw1[(15+2)*16 + j];
#pragma unroll
        for (int l = 0; l < 6; l++) {
            float f = (float)(1 << l);
            int rs = 15 + 3 + 6*l;         // sin rows
            acc += __sinf(v0*f) * dw1[(rs+0)*16 + j];
            acc += __sinf(v1*f) * dw1[(rs+1)*16 + j];
            acc += __sinf(v2*f) * dw1[(rs+2)*16 + j];
            acc += __cosf(v0*f) * dw1[(rs+3)*16 + j];
            acc += __cosf(v1*f) * dw1[(rs+4)*16 + j];
            acc += __cosf(v2*f) * dw1[(rs+5)*16 + j];
        }
        s_embw[j] = acc;
    } else if (tid == 16) {
        float o[3], d[3];
#pragma unroll
        for (int c = 0; c < 3; c++) { o[c] = ro[3*ray+c]; d[c] = rd[3*ray+c]; }
        float tmin = -1e30f, tmax = 1e30f;
#pragma unroll
        for (int c = 0; c < 3; c++) {
            float vec = (d[c] == 0.0f) ? 1e-6f : d[c];
            float ra = ( 1.0f - o[c]) / vec;
            float rb = (-1.0f - o[c]) / vec;
            tmin = fmaxf(tmin, fminf(ra, rb));
            tmax = fminf(tmax, fmaxf(ra, rb));
        }
        tmin = fminf(fmaxf(tmin, NEAR_T), FAR_T);
        tmax = fminf(fmaxf(tmax, NEAR_T), FAR_T);
        s_rc[0] = tmin;
        s_rc[1] = sqrtf(d[0]*d[0] + d[1]*d[1] + d[2]*d[2]);
        s_rc[2] = (tmax <= tmin) ? 1.0f : 0.0f;
        s_rc[3] = o[0]; s_rc[4] = o[1]; s_rc[5] = o[2];
        s_rc[6] = d[0]; s_rc[7] = d[1]; s_rc[8] = d[2];
    }
    __syncthreads();

    const float tmin = s_rc[0], dn = s_rc[1], mask = s_rc[2];
    const float ox = s_rc[3], oy = s_rc[4], oz = s_rc[5];
    const float dx = s_rc[6], dy = s_rc[7], dz = s_rc[8];
    const float inv_dn = 1.0f / dn;

    for (int s = tid; s < NS; s += 128) {
        float4 outv = make_float4(0.0f, 0.0f, 0.0f, 0.0f);
        if (mask == 0.0f) {
            float interpx = tmin + (STEPW * (float)s) * inv_dn;
            float px = fmaf(dx, interpx, ox);
            float py = fmaf(dy, interpx, oy);
            float pz = fmaf(dz, interpx, oz);
            if (fabsf(px) <= 1.0f && fabsf(py) <= 1.0f && fabsf(pz) <= 1.0f) {
                float tx = (px + 1.0f) * 0.5f;
                float ty = (py + 1.0f) * 0.5f;
                float tz = (pz + 1.0f) * 0.5f;
                float gx = tx * 159.0f, gy = ty * 159.0f, gz = tz * 159.0f;
                float fx0 = floorf(gx), fy0 = floorf(gy), fz0 = floorf(gz);
                float fx = gx - fx0, fy = gy - fy0, fz = gz - fz0;
                int x0 = min(max((int)fx0, 0), RES-1);
                int y0 = min(max((int)fy0, 0), RES-1);
                int z0 = min(max((int)fz0, 0), RES-1);
                int x1 = min(x0 + 1, RES-1);
                int y1 = min(y0 + 1, RES-1);
                int z1 = min(z0 + 1, RES-1);
                int b00 = x0*RES2 + y0*RES;
                int b01 = x0*RES2 + y1*RES;
                int b10 = x1*RES2 + y0*RES;
                int b11 = x1*RES2 + y1*RES;
                float w000 = (1-fx)*(1-fy)*(1-fz);
                float w001 = (1-fx)*(1-fy)*fz;
                float w010 = (1-fx)*fy*(1-fz);
                float w011 = (1-fx)*fy*fz;
                float w100 = fx*(1-fy)*(1-fz);
                float w101 = fx*(1-fy)*fz;
                float w110 = fx*fy*(1-fz);
                float w111 = fx*fy*fz;
                float lat[12];
#pragma unroll
                for (int c = 0; c < 12; c++) {
                    const float* g = grid + c * RES3;
                    lat[c] = g[b00+z0]*w000 + g[b00+z1]*w001
                           + g[b01+z0]*w010 + g[b01+z1]*w011
                           + g[b10+z0]*w100 + g[b10+z1]*w101
                           + g[b11+z0]*w110 + g[b11+z1]*w111;
                }

                // ---- attention MLP ----
                float ain[15];
                ain[0] = 2.0f*tz - 1.0f;
                ain[1] = 2.0f*ty - 1.0f;
                ain[2] = 2.0f*tx - 1.0f;
#pragma unroll
                for (int c = 0; c < 12; c++) ain[3+c] = lat[c];

                float h1[32], h2[32], lg[4];
                mlp_layer<15, 32, true >(ain, s_aw1, s_ab1, h1);
                mlp_layer<32, 32, true >(h1,  s_aw2, s_ab2, h2);
                mlp_layer<32, 4,  false>(h2,  s_aw3, s_ab3, lg);

                float mx = fmaxf(fmaxf(lg[0], lg[1]), fmaxf(lg[2], lg[3]));
                float e0 = __expf(lg[0]-mx), e1 = __expf(lg[1]-mx),
                      e2 = __expf(lg[2]-mx), e3 = __expf(lg[3]-mx);
                float att1 = __fdividef(e1, e0 + e1 + e2 + e3);

                // ---- pos MLP ----
                float p1[16], p2[16], pos[16];
                mlp_layer<12, 16, true >(lat, s_pw1, s_pb1, p1);
                mlp_layer<16, 16, true >(p1,  s_pw2, s_pb2, p2);
                mlp_layer<16, 16, false>(p2,  s_pw3, s_pb3, pos);

                // ---- decoder MLP (emb part folded into s_embw bias) ----
                float d1[16], d2[16], d3[16];
                mlp_layer<15, 16, true>(pos + 1, s_dw1, s_embw, d1);
                mlp_layer<16, 16, true>(d1,      s_dw2, s_db2,  d2);
                mlp_layer<16, 16, true>(d2,      s_dw3, s_db3,  d3);

                float rr0 = s_db4[0], rr1 = s_db4[1], rr2 = s_db4[2];
#pragma unroll
                for (int k = 0; k < 16; k++) {
                    float a = d3[k];
                    rr0 = fmaf(a, s_dw4[k*3+0], rr0);
                    rr1 = fmaf(a, s_dw4[k*3+1], rr1);
                    rr2 = fmaf(a, s_dw4[k*3+2], rr2);
                }

                float dens = att1 * pos[0];
                float xs = dens + ACT_SHIFT_F;
                float e = __expf(-fabsf(xs));
                float sp = fmaxf(xs, 0.0f) + __logf(1.0f + e);
                outv.x = 1.0f - __expf(-sp * 0.5f);
                outv.y = __fdividef(1.0f, 1.0f + __expf(-att1 * rr0));
                outv.z = __fdividef(1.0f, 1.0f + __expf(-att1 * rr1));
                outv.w = __fdividef(1.0f, 1.0f + __expf(-att1 * rr2));
            }
        }
        s_samp[s] = outv;
    }
    __syncthreads();

    // ---- composite by warp 0 ----
    if (tid < 32) {
        const int lane = tid;
        const float tmindn = tmin * dn;
        float T = 1.0f;
        float sr = 0.f, sg = 0.f, sb = 0.f, sd = 0.f, sa = 0.f;
        for (int s0 = 0; s0 < NS; s0 += 32) {
            int s = s0 + lane;
            float4 v = (s < NS) ? s_samp[s] : make_float4(0.f, 0.f, 0.f, 0.f);
            float p = fmaxf(1.0f - v.x, 1e-10f);
#pragma unroll
            for (int off = 1; off < 32; off <<= 1) {
                float n = __shfl_up_sync(0xffffffffu, p, off);
                if (lane >= off) p *= n;
            }
            float excl = __shfl_up_sync(0xffffffffu, p, 1);
            if (lane == 0) excl = 1.0f;
            float w = v.x * T * excl;
            float depth = tmindn + STEPW * (float)s;
            sr += w * v.y; sg += w * v.z; sb += w * v.w;
            sd += w * depth; sa += w;
            T *= __shfl_sync(0xffffffffu, p, 31);
        }
#pragma unroll
        for (int off = 16; off; off >>= 1) {
            sr += __shfl_xor_sync(0xffffffffu, sr, off);
            sg += __shfl_xor_sync(0xffffffffu, sg, off);
            sb += __shfl_xor_sync(0xffffffffu, sb, off);
            sd += __shfl_xor_sync(0xffffffffu, sd, off);
            sa += __shfl_xor_sync(0xffffffffu, sa, off);
        }
        if (lane == 0) {
            float depthm = sd + T * FAR_T;
            out[ray*6 + 0] = sr + T;     // + T * BG (BG = 1)
            out[ray*6 + 1] = sg + T;
            out[ray*6 + 2] = sb + T;
            out[ray*6 + 3] = depthm;
            out[ray*6 + 4] = 1.0f / depthm;
            out[ray*6 + 5] = sa;
        }
    }
}

// ---------------------------------------------------------------------------
extern "C" void kernel_launch(void* const* d_in, const int* in_sizes, int n_in,
                              void* d_out, int out_size)
{
    const float* ro  = (const float*)d_in[0];
    const float* rd  = (const float*)d_in[1];
    const float* vd  = (const float*)d_in[2];
    const float* grd = (const float*)d_in[3];
    const float* aw1 = (const float*)d_in[4];  const float* ab1 = (const float*)d_in[5];
    const float* aw2 = (const float*)d_in[6];  const float* ab2 = (const float*)d_in[7];
    const float* aw3 = (const float*)d_in[8];  const float* ab3 = (const float*)d_in[9];
    const float* pw1 = (const float*)d_in[10]; const float* pb1 = (const float*)d_in[11];
    const float* pw2 = (const float*)d_in[12]; const float* pb2 = (const float*)d_in[13];
    const float* pw3 = (const float*)d_in[14]; const float* pb3 = (const float*)d_in[15];
    const float* dw1 = (const float*)d_in[16]; const float* db1 = (const float*)d_in[17];
    const float* dw2 = (const float*)d_in[18]; const float* db2 = (const float*)d_in[19];
    const float* dw3 = (const float*)d_in[20]; const float* db3 = (const float*)d_in[21];
    const float* dw4 = (const float*)d_in[22]; const float* db4 = (const float*)d_in[23];
    float* out = (float*)d_out;

    fused_kernel<<<NRAYS, 128>>>(ro, rd, vd, grd,
                                 aw1, ab1, aw2, ab2, aw3, ab3,
                                 pw1, pb1, pw2, pb2, pw3, pb3,
                                 dw1, db1, dw2, db2, dw3, db3, dw4, db4,
                                 out);
}